// round 4
// baseline (speedup 1.0000x reference)
#include <cuda_runtime.h>

#define N_NODES 50000
#define N_EDGES 200000

// Scratch: per-node accumulator, layout [node][lane u (32)][12 floats]:
//   slot 0..3 : { f0,  f1x, f1y, f1z }
//   slot 4..7 : { p00, dot, p01x, p01y }
//   slot 8..11: { p01z, p10x, p10y, p10z }
// 50000 * 384 floats = 76.8 MB (L2-resident on GB300).
__device__ __align__(16) float g_sums[(size_t)N_NODES * 384];
__device__ float g_cnt[N_NODES];

__global__ void zero_kernel() {
    int i = blockIdx.x * 256 + threadIdx.x;
    if (i < N_NODES * 96) ((float4*)g_sums)[i] = make_float4(0.f, 0.f, 0.f, 0.f);
    if (i < N_NODES) g_cnt[i] = 0.f;
}

// One warp per edge. Lane u handles channel u (MUL=32).
__global__ __launch_bounds__(256) void edge_kernel(
    const float* __restrict__ nf,
    const float4* __restrict__ sh,
    const int* __restrict__ senders,
    const int* __restrict__ receivers)
{
    int warp = threadIdx.x >> 5;
    int lane = threadIdx.x & 31;
    int e = blockIdx.x * 8 + warp;
    if (e >= N_EDGES) return;

    int s = __ldg(senders + e);
    int r = __ldg(receivers + e);
    float4 q = __ldg(sh + e);
    float s0 = q.x, s1x = q.y, s1y = q.z, s1z = q.w;

    const float* p = nf + (size_t)s * 128;
    float f0  = __ldg(p + lane);
    float f1x = __ldg(p + 32 + 3 * lane);
    float f1y = __ldg(p + 33 + 3 * lane);
    float f1z = __ldg(p + 34 + 3 * lane);

    float p00 = s0 * f0;
    // dot = (s1 . f1) / sqrt(3)
    float dot = (s1x * f1x + s1y * f1y + s1z * f1z) * 0.5773502691896258f;

    unsigned long long gp = (unsigned long long)__cvta_generic_to_global(
        g_sums + (size_t)r * 384 + lane * 12);

    asm volatile("red.global.add.v4.f32 [%0], {%1,%2,%3,%4};"
                 :: "l"(gp), "f"(f0), "f"(f1x), "f"(f1y), "f"(f1z) : "memory");
    asm volatile("red.global.add.v4.f32 [%0], {%1,%2,%3,%4};"
                 :: "l"(gp + 16), "f"(p00), "f"(dot), "f"(s0 * f1x), "f"(s0 * f1y) : "memory");
    asm volatile("red.global.add.v4.f32 [%0], {%1,%2,%3,%4};"
                 :: "l"(gp + 32), "f"(s0 * f1z), "f"(f0 * s1x), "f"(f0 * s1y), "f"(f0 * s1z) : "memory");

    if (lane == 0) atomicAdd(&g_cnt[r], 1.0f);
}

// One warp per node. Lane v computes output channel v: o0[v] and o1[v][xyz].
// Combined weights fold the self-connection and all normalizations except the
// per-node scatter-mean scale, which is applied at the very end.
__global__ __launch_bounds__(256) void node_kernel(
    const float* __restrict__ W0, const float* __restrict__ W1,
    const float* __restrict__ Ws0, const float* __restrict__ Ws1,
    float* __restrict__ out)
{
    __shared__ float2 Wc[96 * 32];      // {W0c, W1c}
    __shared__ float4 inA[8][96];       // {in0[k], in1[k].xyz}

    const float inv96 = 0.10206207261596577f;   // 1/sqrt(96)
    const float sc32  = 0.26516504294495533f;   // 1.5/sqrt(32)

    for (int idx = threadIdx.x; idx < 96 * 32; idx += 256) {
        float w0 = __ldg(W0 + idx) * inv96;
        float w1 = __ldg(W1 + idx) * inv96;
        if (idx < 32 * 32) {
            w0 += __ldg(Ws0 + idx) * sc32;
            w1 += __ldg(Ws1 + idx) * sc32;
        }
        Wc[idx] = make_float2(w0, w1);
    }
    __syncthreads();

    int warp = threadIdx.x >> 5;
    int lane = threadIdx.x & 31;
    int n = blockIdx.x * 8 + warp;
    if (n >= N_NODES) return;

    const float4* sp = (const float4*)(g_sums + (size_t)n * 384);
    float4 a = sp[lane * 3 + 0];
    float4 b = sp[lane * 3 + 1];
    float4 c = sp[lane * 3 + 2];

    inA[warp][lane]      = a;                                 // { f0,  f1x,  f1y,  f1z  }
    inA[warp][32 + lane] = make_float4(b.x, b.z, b.w, c.x);   // { p00, p01x, p01y, p01z }
    inA[warp][64 + lane] = make_float4(b.y, c.y, c.z, c.w);   // { dot, p10x, p10y, p10z }
    __syncwarp();

    float acc0 = 0.f, ax = 0.f, ay = 0.f, az = 0.f;
    #pragma unroll
    for (int k = 0; k < 96; k++) {
        float4 iv = inA[warp][k];          // broadcast LDS.128
        float2 w  = Wc[k * 32 + lane];     // coalesced LDS.64
        acc0 += iv.x * w.x;
        ax   += iv.y * w.y;
        ay   += iv.z * w.y;
        az   += iv.w * w.y;
    }

    float cnt = g_cnt[n];
    float scale = 1.0f / (1.5f * fmaxf(cnt, 1.0f));

    float* o = out + (size_t)n * 128;
    o[lane]            = acc0 * scale;
    o[32 + 3 * lane]   = ax * scale;
    o[33 + 3 * lane]   = ay * scale;
    o[34 + 3 * lane]   = az * scale;
}

extern "C" void kernel_launch(void* const* d_in, const int* in_sizes, int n_in,
                              void* d_out, int out_size) {
    const float*  nf        = (const float*) d_in[0];
    const float4* sh        = (const float4*)d_in[1];
    const int*    senders   = (const int*)   d_in[2];
    const int*    receivers = (const int*)   d_in[3];
    const float*  W0        = (const float*) d_in[4];
    const float*  W1        = (const float*) d_in[5];
    const float*  Ws0       = (const float*) d_in[6];
    const float*  Ws1       = (const float*) d_in[7];
    float* out = (float*)d_out;

    zero_kernel<<<(N_NODES * 96 + 255) / 256, 256>>>();
    edge_kernel<<<(N_EDGES + 7) / 8, 256>>>(nf, sh, senders, receivers);
    node_kernel<<<(N_NODES + 7) / 8, 256>>>(W0, W1, Ws0, Ws1, out);
}

// round 5
// speedup vs baseline: 1.1028x; 1.1028x over previous
#include <cuda_runtime.h>

#define N_NODES 50000
#define N_EDGES 200000

// CSR scratch (static __device__ — no allocations).
__device__ int g_cnt[N_NODES];                    // histogram, then fill cursor
__device__ int g_off[N_NODES + 1];                // row offsets
__device__ int g_send[N_EDGES];                   // CSR slot -> sender id
__device__ __align__(16) float4 g_sh[N_EDGES];    // CSR slot -> sh (s0, s1x, s1y, s1z)

__global__ void hist_zero_kernel() {
    int i = blockIdx.x * 256 + threadIdx.x;
    if (i < N_NODES) g_cnt[i] = 0;
}

__global__ void hist_kernel(const int* __restrict__ receivers) {
    int e = blockIdx.x * 256 + threadIdx.x;
    if (e < N_EDGES) atomicAdd(&g_cnt[receivers[e]], 1);
}

// Single-block exclusive scan over 50K counts; leaves g_off = offsets and
// resets g_cnt to the row start (fill cursor).
__global__ __launch_bounds__(1024) void scan_kernel() {
    const int T = 1024;
    const int PER = (N_NODES + T - 1) / T;   // 49
    __shared__ int sums[T];
    int t = threadIdx.x;
    int base = t * PER;

    int s = 0;
    #pragma unroll 7
    for (int j = 0; j < PER; j++) {
        int idx = base + j;
        if (idx < N_NODES) s += g_cnt[idx];
    }
    sums[t] = s;
    __syncthreads();
    for (int d = 1; d < T; d <<= 1) {
        int v = (t >= d) ? sums[t - d] : 0;
        __syncthreads();
        sums[t] += v;
        __syncthreads();
    }
    int run = (t == 0) ? 0 : sums[t - 1];
    for (int j = 0; j < PER; j++) {
        int idx = base + j;
        if (idx < N_NODES) {
            int c = g_cnt[idx];
            g_off[idx] = run;
            g_cnt[idx] = run;   // becomes fill cursor
            run += c;
        }
    }
    if (t == T - 1) g_off[N_NODES] = run;
}

__global__ void fill_kernel(const int* __restrict__ senders,
                            const int* __restrict__ receivers,
                            const float4* __restrict__ sh) {
    int e = blockIdx.x * 256 + threadIdx.x;
    if (e >= N_EDGES) return;
    int r = receivers[e];
    int pos = atomicAdd(&g_cnt[r], 1);
    g_send[pos] = senders[e];
    g_sh[pos]   = __ldg(sh + e);
}

// One warp per node. Phase 1: accumulate the 12 per-lane tensor-product sums
// in registers over the node's CSR edge range. Phase 2: the proven GEMM loop
// (combined weights fold self-connection + all static normalizations; the
// per-node 1/(1.5*max(deg,1)) scale is applied at the end).
__global__ __launch_bounds__(256) void node_fused_kernel(
    const float* __restrict__ nf,
    const float* __restrict__ W0, const float* __restrict__ W1,
    const float* __restrict__ Ws0, const float* __restrict__ Ws1,
    float* __restrict__ out)
{
    __shared__ float2 Wc[96 * 32];      // {W0c, W1c}
    __shared__ float4 inA[8][96];       // {in0[k], in1[k].xyz}

    const float inv96 = 0.10206207261596577f;   // 1/sqrt(96)
    const float sc32  = 0.26516504294495533f;   // 1.5/sqrt(32)

    for (int idx = threadIdx.x; idx < 96 * 32; idx += 256) {
        float w0 = __ldg(W0 + idx) * inv96;
        float w1 = __ldg(W1 + idx) * inv96;
        if (idx < 32 * 32) {
            w0 += __ldg(Ws0 + idx) * sc32;
            w1 += __ldg(Ws1 + idx) * sc32;
        }
        Wc[idx] = make_float2(w0, w1);
    }
    __syncthreads();

    int warp = threadIdx.x >> 5;
    int lane = threadIdx.x & 31;
    int n = blockIdx.x * 8 + warp;          // grid 6250*8 == 50000 exactly

    int start = g_off[n];
    int end   = g_off[n + 1];

    float A0 = 0.f, A1x = 0.f, A1y = 0.f, A1z = 0.f;     // sum f0, f1
    float B0 = 0.f, B1x = 0.f, B1y = 0.f, B1z = 0.f;     // sum s0*f0, s0*f1
    float D  = 0.f, C1x = 0.f, C1y = 0.f, C1z = 0.f;     // sum s1.f1, f0*s1

    for (int base = start; base < end; base += 32) {
        int m = end - base;
        if (m > 32) m = 32;
        int   sl = 0;
        float4 ql = make_float4(0.f, 0.f, 0.f, 0.f);
        if (lane < m) {
            sl = __ldg(g_send + base + lane);   // coalesced
            ql = g_sh[base + lane];             // coalesced 16B
        }
        for (int i = 0; i < m; i++) {
            int   s   = __shfl_sync(0xffffffffu, sl,   i);
            float s0  = __shfl_sync(0xffffffffu, ql.x, i);
            float t1x = __shfl_sync(0xffffffffu, ql.y, i);
            float t1y = __shfl_sync(0xffffffffu, ql.z, i);
            float t1z = __shfl_sync(0xffffffffu, ql.w, i);
            const float* p = nf + (size_t)s * 128;
            float f0  = __ldg(p + lane);
            float f1x = __ldg(p + 32 + 3 * lane);
            float f1y = __ldg(p + 33 + 3 * lane);
            float f1z = __ldg(p + 34 + 3 * lane);
            A0  += f0;        A1x += f1x;       A1y += f1y;       A1z += f1z;
            B0  += s0 * f0;   B1x += s0 * f1x;  B1y += s0 * f1y;  B1z += s0 * f1z;
            D   += t1x * f1x + t1y * f1y + t1z * f1z;
            C1x += f0 * t1x;  C1y += f0 * t1y;  C1z += f0 * t1z;
        }
    }
    D *= 0.5773502691896258f;   // 1/sqrt(3)

    inA[warp][lane]      = make_float4(A0, A1x, A1y, A1z);   // k 0..31
    inA[warp][32 + lane] = make_float4(B0, B1x, B1y, B1z);   // k 32..63 (p00 | p01)
    inA[warp][64 + lane] = make_float4(D,  C1x, C1y, C1z);   // k 64..95 (dot | p10)
    __syncwarp();

    float acc0 = 0.f, ax = 0.f, ay = 0.f, az = 0.f;
    #pragma unroll
    for (int k = 0; k < 96; k++) {
        float4 iv = inA[warp][k];          // broadcast LDS.128
        float2 w  = Wc[k * 32 + lane];     // coalesced LDS.64
        acc0 += iv.x * w.x;
        ax   += iv.y * w.y;
        ay   += iv.z * w.y;
        az   += iv.w * w.y;
    }

    int deg = end - start;
    float scale = 1.0f / (1.5f * fmaxf((float)deg, 1.0f));

    float* o = out + (size_t)n * 128;
    o[lane]            = acc0 * scale;
    o[32 + 3 * lane]   = ax * scale;
    o[33 + 3 * lane]   = ay * scale;
    o[34 + 3 * lane]   = az * scale;
}

extern "C" void kernel_launch(void* const* d_in, const int* in_sizes, int n_in,
                              void* d_out, int out_size) {
    const float*  nf        = (const float*) d_in[0];
    const float4* sh        = (const float4*)d_in[1];
    const int*    senders   = (const int*)   d_in[2];
    const int*    receivers = (const int*)   d_in[3];
    const float*  W0        = (const float*) d_in[4];
    const float*  W1        = (const float*) d_in[5];
    const float*  Ws0       = (const float*) d_in[6];
    const float*  Ws1       = (const float*) d_in[7];
    float* out = (float*)d_out;

    hist_zero_kernel<<<(N_NODES + 255) / 256, 256>>>();
    hist_kernel<<<(N_EDGES + 255) / 256, 256>>>(receivers);
    scan_kernel<<<1, 1024>>>();
    fill_kernel<<<(N_EDGES + 255) / 256, 256>>>(senders, receivers, sh);
    node_fused_kernel<<<N_NODES / 8, 256>>>(nf, W0, W1, Ws0, Ws1, out);
}

// round 8
// speedup vs baseline: 1.6486x; 1.4949x over previous
#include <cuda_runtime.h>

#define N_NODES 50000
#define N_EDGES 200000
#define NB 2
#define WARPS 8
#define NODES_PER_BLOCK (WARPS * NB)                       // 16
#define GRID_NODE ((N_NODES + NODES_PER_BLOCK - 1) / NODES_PER_BLOCK)  // 3125

// CSR scratch (static __device__ — no allocations).
__device__ int g_cnt[N_NODES];                    // histogram, then fill cursor
__device__ int g_off[N_NODES + 1];                // row offsets
__device__ int g_send[N_EDGES];                   // CSR slot -> sender id
__device__ __align__(16) float4 g_sh[N_EDGES];    // CSR slot -> sh

__global__ void hist_zero_kernel() {
    int i = blockIdx.x * 256 + threadIdx.x;
    if (i < N_NODES) g_cnt[i] = 0;
}

__global__ void hist_kernel(const int* __restrict__ receivers) {
    int e = blockIdx.x * 256 + threadIdx.x;
    if (e < N_EDGES) atomicAdd(&g_cnt[receivers[e]], 1);
}

// Single-block tiled exclusive scan, coalesced. Leaves g_off = offsets,
// g_cnt = row-start fill cursors.
__global__ __launch_bounds__(1024) void scan_kernel() {
    __shared__ int warp_sums[32];
    int tid = threadIdx.x, lane = tid & 31, wid = tid >> 5;
    int running = 0;
    const int NT = (N_NODES + 1023) / 1024;   // 49 tiles
    for (int t = 0; t < NT; t++) {
        int i = t * 1024 + tid;
        int v = (i < N_NODES) ? g_cnt[i] : 0;
        int x = v;
        #pragma unroll
        for (int d = 1; d < 32; d <<= 1) {
            int y = __shfl_up_sync(0xffffffffu, x, d);
            if (lane >= d) x += y;
        }
        if (lane == 31) warp_sums[wid] = x;
        __syncthreads();
        if (wid == 0) {
            int s = warp_sums[lane];
            #pragma unroll
            for (int d = 1; d < 32; d <<= 1) {
                int y = __shfl_up_sync(0xffffffffu, s, d);
                if (lane >= d) s += y;
            }
            warp_sums[lane] = s;
        }
        __syncthreads();
        int warp_excl = (wid == 0) ? 0 : warp_sums[wid - 1];
        int excl = running + warp_excl + (x - v);
        if (i < N_NODES) { g_off[i] = excl; g_cnt[i] = excl; }
        running += warp_sums[31];
        __syncthreads();
    }
    if (tid == 0) g_off[N_NODES] = running;
}

__global__ void fill_kernel(const int* __restrict__ senders,
                            const int* __restrict__ receivers,
                            const float4* __restrict__ sh) {
    int e = blockIdx.x * 256 + threadIdx.x;
    if (e >= N_EDGES) return;
    int r = receivers[e];
    int pos = atomicAdd(&g_cnt[r], 1);
    g_send[pos] = senders[e];
    g_sh[pos]   = __ldg(sh + e);
}

// One warp handles NB=2 consecutive nodes. Phase 1: per node, accumulate the
// 12 per-lane tensor-product sums in registers over the CSR edge range, then
// park them in smem. Phase 2: GEMM with the combined weight tile, amortized
// over both nodes (weights folded: self-connection + static norms; per-node
// 1/(1.5*max(deg,1)) applied at the end).
__global__ __launch_bounds__(256) void node_fused_kernel(
    const float* __restrict__ nf,
    const float* __restrict__ W0, const float* __restrict__ W1,
    const float* __restrict__ Ws0, const float* __restrict__ Ws1,
    float* __restrict__ out)
{
    __shared__ float2 Wc[96 * 32];          // 24576 B
    __shared__ float4 inA[WARPS][NB][96];   // 24576 B   (total = 48 KB exactly)

    const float inv96 = 0.10206207261596577f;   // 1/sqrt(96)
    const float sc32  = 0.26516504294495533f;   // 1.5/sqrt(32)

    for (int idx = threadIdx.x; idx < 96 * 32; idx += 256) {
        float w0 = __ldg(W0 + idx) * inv96;
        float w1 = __ldg(W1 + idx) * inv96;
        if (idx < 32 * 32) {
            w0 += __ldg(Ws0 + idx) * sc32;
            w1 += __ldg(Ws1 + idx) * sc32;
        }
        Wc[idx] = make_float2(w0, w1);
    }
    __syncthreads();

    int warp = threadIdx.x >> 5;
    int lane = threadIdx.x & 31;
    int base = blockIdx.x * NODES_PER_BLOCK + warp * NB;
    if (base >= N_NODES) return;

    int off0 = lane;
    int off1 = 32 + 3 * lane;

    int deg[NB];

    #pragma unroll
    for (int b = 0; b < NB; b++) {
        int n = base + b;
        if (n >= N_NODES) { deg[b] = -1; continue; }
        int js = g_off[n];
        int je = g_off[n + 1];
        deg[b] = je - js;

        float A0 = 0.f, A1x = 0.f, A1y = 0.f, A1z = 0.f;   // sum f0, f1
        float B0 = 0.f, B1x = 0.f, B1y = 0.f, B1z = 0.f;   // sum s0*f0, s0*f1
        float D  = 0.f, C1x = 0.f, C1y = 0.f, C1z = 0.f;   // sum s1.f1, f0*s1

        #pragma unroll 2
        for (int j = js; j < je; j++) {
            int    s = __ldg(g_send + j);      // uniform broadcast load
            float4 q = __ldg(g_sh + j);        // uniform broadcast 16B
            const float* p = nf + (size_t)s * 128;
            float f0  = __ldg(p + off0);
            float f1x = __ldg(p + off1);
            float f1y = __ldg(p + off1 + 1);
            float f1z = __ldg(p + off1 + 2);
            A0  += f0;          A1x += f1x;        A1y += f1y;        A1z += f1z;
            B0  += q.x * f0;    B1x += q.x * f1x;  B1y += q.x * f1y;  B1z += q.x * f1z;
            D   += q.y * f1x + q.z * f1y + q.w * f1z;
            C1x += f0 * q.y;    C1y += f0 * q.z;   C1z += f0 * q.w;
        }
        D *= 0.5773502691896258f;   // 1/sqrt(3)

        inA[warp][b][lane]      = make_float4(A0, A1x, A1y, A1z);   // k 0..31
        inA[warp][b][32 + lane] = make_float4(B0, B1x, B1y, B1z);   // k 32..63
        inA[warp][b][64 + lane] = make_float4(D,  C1x, C1y, C1z);   // k 64..95
    }
    __syncwarp();

    float o0[NB], ox[NB], oy[NB], oz[NB];
    #pragma unroll
    for (int b = 0; b < NB; b++) { o0[b] = ox[b] = oy[b] = oz[b] = 0.f; }

    #pragma unroll 8
    for (int k = 0; k < 96; k++) {
        float2 w = Wc[k * 32 + lane];          // coalesced LDS.64
        #pragma unroll
        for (int b = 0; b < NB; b++) {
            float4 iv = inA[warp][b][k];       // broadcast LDS.128
            o0[b] += iv.x * w.x;
            ox[b] += iv.y * w.y;
            oy[b] += iv.z * w.y;
            oz[b] += iv.w * w.y;
        }
    }

    #pragma unroll
    for (int b = 0; b < NB; b++) {
        int n = base + b;
        if (n >= N_NODES) continue;
        float scale = 1.0f / (1.5f * fmaxf((float)deg[b], 1.0f));
        float* o = out + (size_t)n * 128;
        o[lane]          = o0[b] * scale;
        o[32 + 3 * lane] = ox[b] * scale;
        o[33 + 3 * lane] = oy[b] * scale;
        o[34 + 3 * lane] = oz[b] * scale;
    }
}

extern "C" void kernel_launch(void* const* d_in, const int* in_sizes, int n_in,
                              void* d_out, int out_size) {
    const float*  nf        = (const float*) d_in[0];
    const float4* sh        = (const float4*)d_in[1];
    const int*    senders   = (const int*)   d_in[2];
    const int*    receivers = (const int*)   d_in[3];
    const float*  W0        = (const float*) d_in[4];
    const float*  W1        = (const float*) d_in[5];
    const float*  Ws0       = (const float*) d_in[6];
    const float*  Ws1       = (const float*) d_in[7];
    float* out = (float*)d_out;

    hist_zero_kernel<<<(N_NODES + 255) / 256, 256>>>();
    hist_kernel<<<(N_EDGES + 255) / 256, 256>>>(receivers);
    scan_kernel<<<1, 1024>>>();
    fill_kernel<<<(N_EDGES + 255) / 256, 256>>>(senders, receivers, sh);
    node_fused_kernel<<<GRID_NODE, 256>>>(nf, W0, W1, Ws0, Ws1, out);
}